// round 15
// baseline (speedup 1.0000x reference)
#include <cuda_runtime.h>
#include <math.h>
#include <stdint.h>

// Problem constants
#define B_   4
#define S_   2048
#define D_   1024
#define H_   16
#define DK_  64
#define DFF_ 4096
#define NTOK (B_*S_)     // 8192 tokens
#define EPS_ 1e-5f

// ---------------------------------------------------------------------------
// Scratch (device globals: allocation-free, allowed by harness rules)
// ---------------------------------------------------------------------------
__device__ float g_h [(size_t)NTOK*D_];   // LN1 output (tf32-rounded)
__device__ float g_q [(size_t)NTOK*D_];
__device__ float g_k [(size_t)NTOK*D_];
__device__ float g_v [(size_t)NTOK*D_];
__device__ float g_at[(size_t)NTOK*D_];   // attention out (tf32-rounded)
__device__ float g_x1[(size_t)NTOK*D_];   // residual (exact f32)
__device__ float g_h2[(size_t)NTOK*D_];   // LN2 output (tf32-rounded)
__device__ float g_ff[(size_t)NTOK*DFF_]; // FFN1 out (tf32-rounded)
// tf32-rounded weight copies
__device__ float g_wq[(size_t)D_*D_];
__device__ float g_wk[(size_t)D_*D_];
__device__ float g_wv[(size_t)D_*D_];
__device__ float g_wo[(size_t)D_*D_];
__device__ float g_w1[(size_t)D_*DFF_];
__device__ float g_w2[(size_t)DFF_*D_];

// ---------------------------------------------------------------------------
// Common TF32 helpers
// ---------------------------------------------------------------------------
__device__ __forceinline__ uint32_t f2tf32(float f) {
    uint32_t u;
    asm("cvt.rna.tf32.f32 %0, %1;" : "=r"(u) : "f"(f));
    return u;
}
__device__ __forceinline__ float rtf(float f) {           // round-to-tf32 (rna), as float
    return __uint_as_float(f2tf32(f));
}

__device__ __forceinline__ void mma_tf32(float* c, const uint32_t* a, const uint32_t* b) {
    asm volatile(
        "mma.sync.aligned.m16n8k8.row.col.f32.tf32.tf32.f32 "
        "{%0,%1,%2,%3}, {%4,%5,%6,%7}, {%8,%9}, {%0,%1,%2,%3};\n"
        : "+f"(c[0]), "+f"(c[1]), "+f"(c[2]), "+f"(c[3])
        : "r"(a[0]), "r"(a[1]), "r"(a[2]), "r"(a[3]),
          "r"(b[0]), "r"(b[1]));
}

__device__ __forceinline__ void cp16(uint32_t saddr, const float* g) {
    asm volatile("cp.async.ca.shared.global [%0], [%1], 16;\n"
                 :: "r"(saddr), "l"(g));
}

// ---------------------------------------------------------------------------
// Weight pre-round: dst[i] = tf32_rna(src[i]); vectorized float4, grid-stride
// ---------------------------------------------------------------------------
__global__ void __launch_bounds__(256) round_w_kernel(
    const float* __restrict__ src, float* __restrict__ dst, int n4)
{
    int i = blockIdx.x * 256 + threadIdx.x;
    int stride = gridDim.x * 256;
    for (; i < n4; i += stride) {
        float4 v = ((const float4*)src)[i];
        v.x = rtf(v.x); v.y = rtf(v.y); v.z = rtf(v.z); v.w = rtf(v.w);
        ((float4*)dst)[i] = v;
    }
}

// ---------------------------------------------------------------------------
// LayerNorm: one block per row; output rounded to tf32 (feeds GEMM A operand)
// ---------------------------------------------------------------------------
__global__ void __launch_bounds__(256) ln_kernel(
    const float* __restrict__ x, const float* __restrict__ g,
    const float* __restrict__ b, float* __restrict__ out)
{
    int row = blockIdx.x;
    int tid = threadIdx.x;
    const float4* xr = (const float4*)(x + (size_t)row * D_);
    float4 xv = xr[tid];

    float s  = xv.x + xv.y + xv.z + xv.w;
    float ss = xv.x*xv.x + xv.y*xv.y + xv.z*xv.z + xv.w*xv.w;

    #pragma unroll
    for (int o = 16; o > 0; o >>= 1) {
        s  += __shfl_xor_sync(0xffffffffu, s,  o);
        ss += __shfl_xor_sync(0xffffffffu, ss, o);
    }
    __shared__ float sh_s[8], sh_ss[8];
    __shared__ float mu_sh, rs_sh;
    if ((tid & 31) == 0) { sh_s[tid >> 5] = s; sh_ss[tid >> 5] = ss; }
    __syncthreads();
    if (tid == 0) {
        float S = 0.f, SS = 0.f;
        #pragma unroll
        for (int i = 0; i < 8; i++) { S += sh_s[i]; SS += sh_ss[i]; }
        float mu  = S / (float)D_;
        float var = SS / (float)D_ - mu * mu;
        mu_sh = mu;
        rs_sh = rsqrtf(var + EPS_);
    }
    __syncthreads();
    float mu = mu_sh, rs = rs_sh;

    const float4* gr = (const float4*)g;
    const float4* br = (const float4*)b;
    float4 gv = gr[tid], bv = br[tid];
    float4 o;
    o.x = rtf((xv.x - mu) * rs * gv.x + bv.x);
    o.y = rtf((xv.y - mu) * rs * gv.y + bv.y);
    o.z = rtf((xv.z - mu) * rs * gv.z + bv.z);
    o.w = rtf((xv.w - mu) * rs * gv.w + bv.w);
    ((float4*)(out + (size_t)row * D_))[tid] = o;
}

// ---------------------------------------------------------------------------
// TF32 tensor-core GEMM, cp.async 4-stage pipeline, 512 threads.
// Block tile 256(m) x 128(n) x 16(k). 16 warps in 4x4, warp tile 64x32.
//   A smem [m][k] stride 20 (u32), cp.async 16B (values pre-rounded to tf32)
//   B smem [k][n] stride 136 (u32), cp.async 16B (values pre-rounded to tf32)
// MMA consumes bits as tf32 — exact, since inputs are pre-rounded.
// EPI bit0=+bias, bit1=relu, bit2=+res, bit3=round-output-to-tf32
// NSEL=3: QKV-fused (B/C selected by n-block group of 8).
// ---------------------------------------------------------------------------
#define STAGES 4
#define PAD2  20
#define PADB2 136
#define SM_A (256*PAD2)                  // 5120 u32 per stage
#define SM_B (16*PADB2)                  // 2176 u32 per stage
#define GSM_U32 (STAGES*(SM_A + SM_B))   // 29184
#define GSM_BYTES (GSM_U32*4)            // 116736

template<int EPI, int NSEL>
__global__ void __launch_bounds__(512, 1) tf32gemm256_kernel(
    int M, int N, int K,
    const float* __restrict__ A,
    const float* __restrict__ B0, const float* __restrict__ B1,
    const float* __restrict__ B2,
    const float* __restrict__ bias, const float* __restrict__ res,
    float* __restrict__ C0, float* __restrict__ C1, float* __restrict__ C2)
{
    extern __shared__ __align__(16) uint32_t gsm[];
    uint32_t* As = gsm;                       // [STAGES][256][PAD2]
    uint32_t* Bs = gsm + STAGES * SM_A;       // [STAGES][16][PADB2]
    uint32_t sA_base = (uint32_t)__cvta_generic_to_shared(As);
    uint32_t sB_base = (uint32_t)__cvta_generic_to_shared(Bs);

    int tid  = threadIdx.x;
    int lane = tid & 31;
    int warp = tid >> 5;
    int wm = (warp >> 2) * 64;        // 4 m-slabs of 64
    int wn = (warp & 3) * 32;         // 4 n-slabs of 32
    int m0 = blockIdx.y * 256;
    int tg = lane & 3;
    int gp = lane >> 2;

    const float* Bm;
    float* C;
    int n0;
    if (NSEL == 3) {
        int nb  = blockIdx.x;
        int sel = nb >> 3;
        n0 = (nb & 7) * 128;
        Bm = (sel == 0) ? B0 : (sel == 1) ? B1 : B2;
        C  = (sel == 0) ? C0 : (sel == 1) ? C1 : C2;
    } else {
        n0 = blockIdx.x * 128;
        Bm = B0;
        C  = C0;
    }

    const float* Abase = A + (size_t)m0 * K;
    const float* Bbase = Bm + n0;

    float acc[4][4][4];
    #pragma unroll
    for (int mt = 0; mt < 4; mt++)
        #pragma unroll
        for (int nt = 0; nt < 4; nt++)
            #pragma unroll
            for (int c = 0; c < 4; c++) acc[mt][nt][c] = 0.f;

    // A: 1024 float4 chunks -> 2/thread. B: 512 chunks -> 1/thread.
    #define PREFETCH(stage, k0) do {                                          \
        if ((k0) < K) {                                                       \
            _Pragma("unroll") for (int i = 0; i < 2; i++) {                   \
                int idx = tid + i*512; int m = idx >> 2; int kq = idx & 3;    \
                cp16(sA_base + (uint32_t)(((stage)*SM_A + m*PAD2 + kq*4)*4),  \
                     Abase + (size_t)m * K + (k0) + kq*4);                    \
            }                                                                 \
            { int idx = tid; int k = idx >> 5; int n4 = idx & 31;             \
              cp16(sB_base + (uint32_t)(((stage)*SM_B + k*PADB2 + n4*4)*4),   \
                   Bbase + (size_t)((k0) + k) * N + n4*4); }                  \
        }                                                                     \
        asm volatile("cp.async.commit_group;\n" ::: "memory");                \
    } while (0)

    PREFETCH(0, 0);
    PREFETCH(1, 16);
    PREFETCH(2, 32);

    int niter = K / 16;
    for (int it = 0; it < niter; it++) {
        asm volatile("cp.async.wait_group %0;\n" :: "n"(STAGES - 2) : "memory");
        __syncthreads();

        PREFETCH((it + STAGES - 1) & 3, (it + STAGES - 1) * 16);

        int s = it & 3;
        const uint32_t* Asl = As + s * SM_A;
        const uint32_t* Bsl = Bs + s * SM_B;

        #pragma unroll
        for (int hf = 0; hf < 16; hf += 8) {
            int kb = hf + tg;
            uint32_t af[4][4];
            #pragma unroll
            for (int mt = 0; mt < 4; mt++) {
                const uint32_t* ap = Asl + (wm + mt*16 + gp)*PAD2 + kb;
                af[mt][0] = ap[0];
                af[mt][1] = ap[8*PAD2];
                af[mt][2] = ap[4];
                af[mt][3] = ap[8*PAD2 + 4];
            }
            uint32_t bf[4][2];
            #pragma unroll
            for (int nt = 0; nt < 4; nt++) {
                const uint32_t* bp = Bsl + kb*PADB2 + wn + nt*8 + gp;
                bf[nt][0] = bp[0];
                bf[nt][1] = bp[4*PADB2];
            }
            #pragma unroll
            for (int mt = 0; mt < 4; mt++)
                #pragma unroll
                for (int nt = 0; nt < 4; nt++)
                    mma_tf32(acc[mt][nt], af[mt], bf[nt]);
        }
    }
    #undef PREFETCH

    // ---- epilogue ----
    #pragma unroll
    for (int mt = 0; mt < 4; mt++) {
        int row0 = m0 + wm + mt*16 + gp;
        #pragma unroll
        for (int nt = 0; nt < 4; nt++) {
            int col = n0 + wn + nt*8 + tg*2;
            #pragma unroll
            for (int hh = 0; hh < 2; hh++) {
                int r = row0 + hh*8;
                size_t off = (size_t)r * N + col;
                float v0 = acc[mt][nt][hh*2 + 0];
                float v1 = acc[mt][nt][hh*2 + 1];
                if (EPI & 1) { v0 += bias[col]; v1 += bias[col + 1]; }
                if (EPI & 2) { v0 = fmaxf(v0, 0.f); v1 = fmaxf(v1, 0.f); }
                if (EPI & 4) { float2 rv = *(const float2*)(res + off);
                               v0 += rv.x; v1 += rv.y; }
                if (EPI & 8) { v0 = rtf(v0); v1 = rtf(v1); }
                float2 ov; ov.x = v0; ov.y = v1;
                *(float2*)(C + off) = ov;
            }
        }
    }
}

// ---------------------------------------------------------------------------
// TF32 tensor-core flash attention (R12 design; output rounded to tf32).
// grid (S/128, B*H), 256 threads (8 warps), BQ=128, BKV=64.
// ---------------------------------------------------------------------------
#define SQS 68
#define SKS 68
#define SVS 72
#define SPS 68
#define OFF_K 8704            // 128*68
#define OFF_V 13056           // + 64*68
#define OFF_P 17664           // + 64*72
#define ATTN_SMEM_U32 26368   // + 128*68
#define ATTN_SMEM_BYTES (ATTN_SMEM_U32 * 4)

__global__ void __launch_bounds__(256, 2) attn_tc_kernel(
    const float* __restrict__ Q, const float* __restrict__ K,
    const float* __restrict__ V, float* __restrict__ O)
{
    extern __shared__ uint32_t smem_u[];
    uint32_t* sQ = smem_u;
    uint32_t* sK = smem_u + OFF_K;
    uint32_t* sV = smem_u + OFF_V;
    uint32_t* sP = smem_u + OFF_P;

    int tid  = threadIdx.x;
    int warp = tid >> 5;
    int lane = tid & 31;
    int gp = lane >> 2;
    int tg = lane & 3;
    int mw = warp * 16;

    int qt = blockIdx.x;
    int bh = blockIdx.y;
    int b  = bh >> 4;
    int h  = bh & 15;
    size_t base = ((size_t)b * S_) * D_ + (size_t)h * DK_;

    for (int i = tid; i < 128 * 16; i += 256) {
        int r = i >> 4, c4 = (i & 15) * 4;
        float4 v = *(const float4*)(Q + base + (size_t)(qt * 128 + r) * D_ + c4);
        uint32_t q4[4];
        q4[0] = f2tf32(v.x * 0.125f); q4[1] = f2tf32(v.y * 0.125f);
        q4[2] = f2tf32(v.z * 0.125f); q4[3] = f2tf32(v.w * 0.125f);
        *(uint4*)(sQ + r * SQS + c4) = *(uint4*)q4;
    }

    float oacc[8][4];
    #pragma unroll
    for (int n = 0; n < 8; n++)
        #pragma unroll
        for (int c = 0; c < 4; c++) oacc[n][c] = 0.f;
    float m_lo = -INFINITY, m_hi = -INFINITY;
    float l_lo = 0.f, l_hi = 0.f;

    for (int kt = 0; kt < S_ / 64; kt++) {
        for (int i = tid; i < 64 * 16; i += 256) {
            int r = i >> 4, c4 = (i & 15) * 4;
            size_t goff = base + (size_t)(kt * 64 + r) * D_ + c4;
            float4 kv = *(const float4*)(K + goff);
            float4 vv = *(const float4*)(V + goff);
            uint32_t k4[4], v4[4];
            k4[0] = f2tf32(kv.x); k4[1] = f2tf32(kv.y);
            k4[2] = f2tf32(kv.z); k4[3] = f2tf32(kv.w);
            v4[0] = f2tf32(vv.x); v4[1] = f2tf32(vv.y);
            v4[2] = f2tf32(vv.z); v4[3] = f2tf32(vv.w);
            *(uint4*)(sK + r * SKS + c4) = *(uint4*)k4;
            *(uint4*)(sV + r * SVS + c4) = *(uint4*)v4;
        }
        __syncthreads();

        float sacc[8][4];
        #pragma unroll
        for (int n = 0; n < 8; n++)
            #pragma unroll
            for (int c = 0; c < 4; c++) sacc[n][c] = 0.f;

        #pragma unroll
        for (int k = 0; k < 8; k++) {
            uint32_t aq[4];
            const uint32_t* qr = sQ + (mw + gp) * SQS + k * 8 + tg;
            aq[0] = qr[0];
            aq[1] = qr[8 * SQS];
            aq[2] = qr[4];
            aq[3] = qr[8 * SQS + 4];
            #pragma unroll
            for (int n = 0; n < 8; n++) {
                uint32_t bk[2];
                const uint32_t* kr = sK + (n * 8 + gp) * SKS + k * 8 + tg;
                bk[0] = kr[0];
                bk[1] = kr[4];
                mma_tf32(sacc[n], aq, bk);
            }
        }

        float mx_lo = -INFINITY, mx_hi = -INFINITY;
        #pragma unroll
        for (int n = 0; n < 8; n++) {
            mx_lo = fmaxf(mx_lo, fmaxf(sacc[n][0], sacc[n][1]));
            mx_hi = fmaxf(mx_hi, fmaxf(sacc[n][2], sacc[n][3]));
        }
        mx_lo = fmaxf(mx_lo, __shfl_xor_sync(0xffffffffu, mx_lo, 1));
        mx_lo = fmaxf(mx_lo, __shfl_xor_sync(0xffffffffu, mx_lo, 2));
        mx_hi = fmaxf(mx_hi, __shfl_xor_sync(0xffffffffu, mx_hi, 1));
        mx_hi = fmaxf(mx_hi, __shfl_xor_sync(0xffffffffu, mx_hi, 2));

        float mn_lo = fmaxf(m_lo, mx_lo);
        float mn_hi = fmaxf(m_hi, mx_hi);
        float f_lo = __expf(m_lo - mn_lo);
        float f_hi = __expf(m_hi - mn_hi);
        m_lo = mn_lo; m_hi = mn_hi;

        float s_lo = 0.f, s_hi = 0.f;
        uint32_t* plo_base = sP + (mw + gp) * SPS + tg * 2;
        #pragma unroll
        for (int n = 0; n < 8; n++) {
            float p0 = __expf(sacc[n][0] - mn_lo);
            float p1 = __expf(sacc[n][1] - mn_lo);
            float p2 = __expf(sacc[n][2] - mn_hi);
            float p3 = __expf(sacc[n][3] - mn_hi);
            s_lo += p0 + p1;
            s_hi += p2 + p3;
            uint32_t* plo = plo_base + n * 8;
            plo[0] = f2tf32(p0); plo[1] = f2tf32(p1);
            plo[8 * SPS] = f2tf32(p2); plo[8 * SPS + 1] = f2tf32(p3);
        }
        s_lo += __shfl_xor_sync(0xffffffffu, s_lo, 1);
        s_lo += __shfl_xor_sync(0xffffffffu, s_lo, 2);
        s_hi += __shfl_xor_sync(0xffffffffu, s_hi, 1);
        s_hi += __shfl_xor_sync(0xffffffffu, s_hi, 2);
        l_lo = l_lo * f_lo + s_lo;
        l_hi = l_hi * f_hi + s_hi;

        #pragma unroll
        for (int n = 0; n < 8; n++) {
            oacc[n][0] *= f_lo; oacc[n][1] *= f_lo;
            oacc[n][2] *= f_hi; oacc[n][3] *= f_hi;
        }

        __syncwarp();

        #pragma unroll
        for (int k = 0; k < 8; k++) {
            uint32_t ap[4];
            const uint32_t* pr = sP + (mw + gp) * SPS + k * 8 + tg;
            ap[0] = pr[0];
            ap[1] = pr[8 * SPS];
            ap[2] = pr[4];
            ap[3] = pr[8 * SPS + 4];
            #pragma unroll
            for (int n = 0; n < 8; n++) {
                uint32_t bv[2];
                const uint32_t* vr = sV + (k * 8 + tg) * SVS + n * 8 + gp;
                bv[0] = vr[0];
                bv[1] = vr[4 * SVS];
                mma_tf32(oacc[n], ap, bv);
            }
        }
        __syncthreads();
    }

    float inv_lo = 1.f / l_lo;
    float inv_hi = 1.f / l_hi;
    int row_lo = qt * 128 + mw + gp;
    #pragma unroll
    for (int n = 0; n < 8; n++) {
        size_t off_lo = base + (size_t)row_lo * D_ + n * 8 + tg * 2;
        float2 o1; o1.x = rtf(oacc[n][0] * inv_lo); o1.y = rtf(oacc[n][1] * inv_lo);
        *(float2*)(O + off_lo) = o1;
        size_t off_hi = off_lo + (size_t)8 * D_;
        float2 o2; o2.x = rtf(oacc[n][2] * inv_hi); o2.y = rtf(oacc[n][3] * inv_hi);
        *(float2*)(O + off_hi) = o2;
    }
}

// ---------------------------------------------------------------------------
// Launch
// ---------------------------------------------------------------------------
extern "C" void kernel_launch(void* const* d_in, const int* in_sizes, int n_in,
                              void* d_out, int out_size)
{
    const float* x   = (const float*)d_in[0];
    const float* wq  = (const float*)d_in[1];
    const float* wk  = (const float*)d_in[2];
    const float* wv  = (const float*)d_in[3];
    const float* wo  = (const float*)d_in[4];
    const float* w1  = (const float*)d_in[5];
    const float* b1  = (const float*)d_in[6];
    const float* w2  = (const float*)d_in[7];
    const float* b2  = (const float*)d_in[8];
    const float* g1  = (const float*)d_in[9];
    const float* be1 = (const float*)d_in[10];
    const float* g2  = (const float*)d_in[11];
    const float* be2 = (const float*)d_in[12];
    float* out = (float*)d_out;

    float *h, *q, *k, *v, *at, *x1, *h2, *ff;
    float *rwq, *rwk, *rwv, *rwo, *rw1, *rw2;
    cudaGetSymbolAddress((void**)&h,  g_h);
    cudaGetSymbolAddress((void**)&q,  g_q);
    cudaGetSymbolAddress((void**)&k,  g_k);
    cudaGetSymbolAddress((void**)&v,  g_v);
    cudaGetSymbolAddress((void**)&at, g_at);
    cudaGetSymbolAddress((void**)&x1, g_x1);
    cudaGetSymbolAddress((void**)&h2, g_h2);
    cudaGetSymbolAddress((void**)&ff, g_ff);
    cudaGetSymbolAddress((void**)&rwq, g_wq);
    cudaGetSymbolAddress((void**)&rwk, g_wk);
    cudaGetSymbolAddress((void**)&rwv, g_wv);
    cudaGetSymbolAddress((void**)&rwo, g_wo);
    cudaGetSymbolAddress((void**)&rw1, g_w1);
    cudaGetSymbolAddress((void**)&rw2, g_w2);

    // >48KB dynamic smem opt-ins (host-side attributes, idempotent)
    cudaFuncSetAttribute(attn_tc_kernel,
                         cudaFuncAttributeMaxDynamicSharedMemorySize,
                         ATTN_SMEM_BYTES);
    cudaFuncSetAttribute(tf32gemm256_kernel<0,3>,
                         cudaFuncAttributeMaxDynamicSharedMemorySize, GSM_BYTES);
    cudaFuncSetAttribute(tf32gemm256_kernel<4,1>,
                         cudaFuncAttributeMaxDynamicSharedMemorySize, GSM_BYTES);
    cudaFuncSetAttribute(tf32gemm256_kernel<11,1>,
                         cudaFuncAttributeMaxDynamicSharedMemorySize, GSM_BYTES);
    cudaFuncSetAttribute(tf32gemm256_kernel<5,1>,
                         cudaFuncAttributeMaxDynamicSharedMemorySize, GSM_BYTES);

    dim3 blk(256);
    dim3 blk512(512);

    // 0) pre-round weights to tf32 (exact truncation downstream)
    round_w_kernel<<<512, blk>>>(wq, rwq, D_*D_/4);
    round_w_kernel<<<512, blk>>>(wk, rwk, D_*D_/4);
    round_w_kernel<<<512, blk>>>(wv, rwv, D_*D_/4);
    round_w_kernel<<<512, blk>>>(wo, rwo, D_*D_/4);
    round_w_kernel<<<1024, blk>>>(w1, rw1, D_*DFF_/4);
    round_w_kernel<<<1024, blk>>>(w2, rw2, DFF_*D_/4);

    // 1) h = LN1(x)  (tf32-rounded output)
    ln_kernel<<<NTOK, blk>>>(x, g1, be1, h);

    // 2-4) q,k,v projections: fused QKV
    tf32gemm256_kernel<0,3><<<dim3(24, NTOK/256), blk512, GSM_BYTES>>>(
        NTOK, D_, D_, h, rwq, rwk, rwv, nullptr, nullptr, q, k, v);

    // 5) attention (flash, tf32 tensor cores; output tf32-rounded)
    attn_tc_kernel<<<dim3(S_ / 128, B_ * H_), blk, ATTN_SMEM_BYTES>>>(q, k, v, at);

    // 6) x1 = x + attn @ wo
    tf32gemm256_kernel<4,1><<<dim3(D_/128, NTOK/256), blk512, GSM_BYTES>>>(
        NTOK, D_, D_, at, rwo, nullptr, nullptr, nullptr, x, x1, nullptr, nullptr);

    // 7) h2 = LN2(x1)  (tf32-rounded output)
    ln_kernel<<<NTOK, blk>>>(x1, g2, be2, h2);

    // 8) ff = relu(h2 @ w1 + b1), rounded to tf32 (EPI 1|2|8 = 11)
    tf32gemm256_kernel<11,1><<<dim3(DFF_/128, NTOK/256), blk512, GSM_BYTES>>>(
        NTOK, DFF_, D_, h2, rw1, nullptr, nullptr, b1, nullptr, ff, nullptr, nullptr);

    // 9) out = x1 + ff @ w2 + b2
    tf32gemm256_kernel<5,1><<<dim3(D_/128, NTOK/256), blk512, GSM_BYTES>>>(
        NTOK, D_, DFF_, ff, rw2, nullptr, nullptr, b2, x1, out, nullptr, nullptr);
}

// round 16
// speedup vs baseline: 1.1837x; 1.1837x over previous
#include <cuda_runtime.h>
#include <math.h>
#include <stdint.h>

// Problem constants
#define B_   4
#define S_   2048
#define D_   1024
#define H_   16
#define DK_  64
#define DFF_ 4096
#define NTOK (B_*S_)     // 8192 tokens
#define EPS_ 1e-5f

// ---------------------------------------------------------------------------
// Scratch (device globals: allocation-free, allowed by harness rules)
// ---------------------------------------------------------------------------
__device__ float g_h [(size_t)NTOK*D_];   // LN1 output (tf32-rounded)
__device__ float g_q [(size_t)NTOK*D_];
__device__ float g_k [(size_t)NTOK*D_];
__device__ float g_v [(size_t)NTOK*D_];
__device__ float g_at[(size_t)NTOK*D_];   // attention out (tf32-rounded)
__device__ float g_x1[(size_t)NTOK*D_];   // residual (exact f32)
__device__ float g_h2[(size_t)NTOK*D_];   // LN2 output (tf32-rounded)
__device__ float g_ff[(size_t)NTOK*DFF_]; // FFN1 out (tf32-rounded)
// tf32-rounded weight copies
__device__ float g_wq[(size_t)D_*D_];
__device__ float g_wk[(size_t)D_*D_];
__device__ float g_wv[(size_t)D_*D_];
__device__ float g_wo[(size_t)D_*D_];
__device__ float g_w1[(size_t)D_*DFF_];
__device__ float g_w2[(size_t)DFF_*D_];

// ---------------------------------------------------------------------------
// Common TF32 helpers
// ---------------------------------------------------------------------------
__device__ __forceinline__ uint32_t f2tf32(float f) {
    uint32_t u;
    asm("cvt.rna.tf32.f32 %0, %1;" : "=r"(u) : "f"(f));
    return u;
}
__device__ __forceinline__ float rtf(float f) {           // round-to-tf32 (rna), as float
    return __uint_as_float(f2tf32(f));
}

__device__ __forceinline__ void mma_tf32(float* c, const uint32_t* a, const uint32_t* b) {
    asm volatile(
        "mma.sync.aligned.m16n8k8.row.col.f32.tf32.tf32.f32 "
        "{%0,%1,%2,%3}, {%4,%5,%6,%7}, {%8,%9}, {%0,%1,%2,%3};\n"
        : "+f"(c[0]), "+f"(c[1]), "+f"(c[2]), "+f"(c[3])
        : "r"(a[0]), "r"(a[1]), "r"(a[2]), "r"(a[3]),
          "r"(b[0]), "r"(b[1]));
}

__device__ __forceinline__ void cp16(uint32_t saddr, const float* g) {
    asm volatile("cp.async.ca.shared.global [%0], [%1], 16;\n"
                 :: "r"(saddr), "l"(g));
}

// ---------------------------------------------------------------------------
// Weight pre-round: dst[i] = tf32_rna(src[i]); float4 per thread, sized grids
// ---------------------------------------------------------------------------
__global__ void __launch_bounds__(256) round_w_kernel(
    const float* __restrict__ src, float* __restrict__ dst, int n4)
{
    int i = blockIdx.x * 256 + threadIdx.x;
    int stride = gridDim.x * 256;
    for (; i < n4; i += stride) {
        float4 v = ((const float4*)src)[i];
        v.x = rtf(v.x); v.y = rtf(v.y); v.z = rtf(v.z); v.w = rtf(v.w);
        ((float4*)dst)[i] = v;
    }
}

// ---------------------------------------------------------------------------
// LayerNorm: one block per row; output rounded to tf32 (feeds GEMM A operand)
// ---------------------------------------------------------------------------
__global__ void __launch_bounds__(256) ln_kernel(
    const float* __restrict__ x, const float* __restrict__ g,
    const float* __restrict__ b, float* __restrict__ out)
{
    int row = blockIdx.x;
    int tid = threadIdx.x;
    const float4* xr = (const float4*)(x + (size_t)row * D_);
    float4 xv = xr[tid];

    float s  = xv.x + xv.y + xv.z + xv.w;
    float ss = xv.x*xv.x + xv.y*xv.y + xv.z*xv.z + xv.w*xv.w;

    #pragma unroll
    for (int o = 16; o > 0; o >>= 1) {
        s  += __shfl_xor_sync(0xffffffffu, s,  o);
        ss += __shfl_xor_sync(0xffffffffu, ss, o);
    }
    __shared__ float sh_s[8], sh_ss[8];
    __shared__ float mu_sh, rs_sh;
    if ((tid & 31) == 0) { sh_s[tid >> 5] = s; sh_ss[tid >> 5] = ss; }
    __syncthreads();
    if (tid == 0) {
        float S = 0.f, SS = 0.f;
        #pragma unroll
        for (int i = 0; i < 8; i++) { S += sh_s[i]; SS += sh_ss[i]; }
        float mu  = S / (float)D_;
        float var = SS / (float)D_ - mu * mu;
        mu_sh = mu;
        rs_sh = rsqrtf(var + EPS_);
    }
    __syncthreads();
    float mu = mu_sh, rs = rs_sh;

    const float4* gr = (const float4*)g;
    const float4* br = (const float4*)b;
    float4 gv = gr[tid], bv = br[tid];
    float4 o;
    o.x = rtf((xv.x - mu) * rs * gv.x + bv.x);
    o.y = rtf((xv.y - mu) * rs * gv.y + bv.y);
    o.z = rtf((xv.z - mu) * rs * gv.z + bv.z);
    o.w = rtf((xv.w - mu) * rs * gv.w + bv.w);
    ((float4*)(out + (size_t)row * D_))[tid] = o;
}

// ---------------------------------------------------------------------------
// TF32 tensor-core GEMM, cp.async 3-stage pipeline, BK=32.
// Block tile 256(m) x 128(n) x 32(k). 256 threads = 8 warps in 4x2,
// warp tile 64x64 = 4x8 m16n8k8 tiles (R14-validated shape).
//   A smem [m][k] stride 36 (u32), cp.async 16B (values pre-rounded to tf32)
//   B smem [k][n] stride 136 (u32), cp.async 16B (values pre-rounded to tf32)
// MMA consumes bits as tf32 — exact, since inputs are pre-rounded.
// EPI bit0=+bias, bit1=relu, bit2=+res, bit3=round-output-to-tf32
// NSEL=3: QKV-fused (B/C selected by n-block group of 8).
// ---------------------------------------------------------------------------
#define STAGES 3
#define PAD2  36
#define PADB2 136
#define SM_A (256*PAD2)                  // 9216 u32 per stage
#define SM_B (32*PADB2)                  // 4352 u32 per stage
#define GSM_U32 (STAGES*(SM_A + SM_B))   // 40704
#define GSM_BYTES (GSM_U32*4)            // 162816

template<int EPI, int NSEL>
__global__ void __launch_bounds__(256, 1) tf32gemm256_kernel(
    int M, int N, int K,
    const float* __restrict__ A,
    const float* __restrict__ B0, const float* __restrict__ B1,
    const float* __restrict__ B2,
    const float* __restrict__ bias, const float* __restrict__ res,
    float* __restrict__ C0, float* __restrict__ C1, float* __restrict__ C2)
{
    extern __shared__ __align__(16) uint32_t gsm[];
    uint32_t* As = gsm;                       // [STAGES][256][PAD2]
    uint32_t* Bs = gsm + STAGES * SM_A;       // [STAGES][32][PADB2]
    uint32_t sA_base = (uint32_t)__cvta_generic_to_shared(As);
    uint32_t sB_base = (uint32_t)__cvta_generic_to_shared(Bs);

    int tid  = threadIdx.x;
    int lane = tid & 31;
    int warp = tid >> 5;
    int wm = (warp >> 1) * 64;        // 4 m-slabs of 64
    int wn = (warp & 1) * 64;         // 2 n-slabs of 64
    int m0 = blockIdx.y * 256;
    int tg = lane & 3;
    int gp = lane >> 2;

    const float* Bm;
    float* C;
    int n0;
    if (NSEL == 3) {
        int nb  = blockIdx.x;
        int sel = nb >> 3;
        n0 = (nb & 7) * 128;
        Bm = (sel == 0) ? B0 : (sel == 1) ? B1 : B2;
        C  = (sel == 0) ? C0 : (sel == 1) ? C1 : C2;
    } else {
        n0 = blockIdx.x * 128;
        Bm = B0;
        C  = C0;
    }

    const float* Abase = A + (size_t)m0 * K;
    const float* Bbase = Bm + n0;

    float acc[4][8][4];
    #pragma unroll
    for (int mt = 0; mt < 4; mt++)
        #pragma unroll
        for (int nt = 0; nt < 8; nt++)
            #pragma unroll
            for (int c = 0; c < 4; c++) acc[mt][nt][c] = 0.f;

    // A tile 256m x 32k: 2048 float4 -> 8/thread (m = idx>>3, kq = idx&7)
    // B tile 32k x 128n: 1024 float4 -> 4/thread (k = idx>>5, n4 = idx&31)
    #define PREFETCH(stage, k0) do {                                          \
        if ((k0) < K) {                                                       \
            _Pragma("unroll") for (int i = 0; i < 8; i++) {                   \
                int idx = tid + i*256; int m = idx >> 3; int kq = idx & 7;    \
                cp16(sA_base + (uint32_t)(((stage)*SM_A + m*PAD2 + kq*4)*4),  \
                     Abase + (size_t)m * K + (k0) + kq*4);                    \
            }                                                                 \
            _Pragma("unroll") for (int i = 0; i < 4; i++) {                   \
                int idx = tid + i*256; int k = idx >> 5; int n4 = idx & 31;   \
                cp16(sB_base + (uint32_t)(((stage)*SM_B + k*PADB2 + n4*4)*4), \
                     Bbase + (size_t)((k0) + k) * N + n4*4);                  \
            }                                                                 \
        }                                                                     \
        asm volatile("cp.async.commit_group;\n" ::: "memory");                \
    } while (0)

    // prologue: 2 stages in flight
    PREFETCH(0, 0);
    PREFETCH(1, 32);

    int niter = K / 32;
    for (int it = 0; it < niter; it++) {
        asm volatile("cp.async.wait_group %0;\n" :: "n"(STAGES - 2) : "memory");
        __syncthreads();

        // refill the stage freed at iteration it-1
        int ps = it + STAGES - 1;
        PREFETCH(ps % 3, ps * 32);

        int s = it % 3;
        const uint32_t* Asl = As + s * SM_A;
        const uint32_t* Bsl = Bs + s * SM_B;

        #pragma unroll
        for (int hf = 0; hf < 32; hf += 8) {
            int kb = hf + tg;
            uint32_t af[4][4];
            #pragma unroll
            for (int mt = 0; mt < 4; mt++) {
                const uint32_t* ap = Asl + (wm + mt*16 + gp)*PAD2 + kb;
                af[mt][0] = ap[0];
                af[mt][1] = ap[8*PAD2];
                af[mt][2] = ap[4];
                af[mt][3] = ap[8*PAD2 + 4];
            }
            uint32_t bf[8][2];
            #pragma unroll
            for (int nt = 0; nt < 8; nt++) {
                const uint32_t* bp = Bsl + kb*PADB2 + wn + nt*8 + gp;
                bf[nt][0] = bp[0];
                bf[nt][1] = bp[4*PADB2];
            }
            #pragma unroll
            for (int mt = 0; mt < 4; mt++)
                #pragma unroll
                for (int nt = 0; nt < 8; nt++)
                    mma_tf32(acc[mt][nt], af[mt], bf[nt]);
        }
    }
    #undef PREFETCH

    // ---- epilogue ----
    #pragma unroll
    for (int mt = 0; mt < 4; mt++) {
        int row0 = m0 + wm + mt*16 + gp;
        #pragma unroll
        for (int nt = 0; nt < 8; nt++) {
            int col = n0 + wn + nt*8 + tg*2;
            #pragma unroll
            for (int hh = 0; hh < 2; hh++) {
                int r = row0 + hh*8;
                size_t off = (size_t)r * N + col;
                float v0 = acc[mt][nt][hh*2 + 0];
                float v1 = acc[mt][nt][hh*2 + 1];
                if (EPI & 1) { v0 += bias[col]; v1 += bias[col + 1]; }
                if (EPI & 2) { v0 = fmaxf(v0, 0.f); v1 = fmaxf(v1, 0.f); }
                if (EPI & 4) { float2 rv = *(const float2*)(res + off);
                               v0 += rv.x; v1 += rv.y; }
                if (EPI & 8) { v0 = rtf(v0); v1 = rtf(v1); }
                float2 ov; ov.x = v0; ov.y = v1;
                *(float2*)(C + off) = ov;
            }
        }
    }
}

// ---------------------------------------------------------------------------
// TF32 tensor-core flash attention (unchanged; output tf32-rounded).
// grid (S/128, B*H), 256 threads (8 warps), BQ=128, BKV=64.
// ---------------------------------------------------------------------------
#define SQS 68
#define SKS 68
#define SVS 72
#define SPS 68
#define OFF_K 8704            // 128*68
#define OFF_V 13056           // + 64*68
#define OFF_P 17664           // + 64*72
#define ATTN_SMEM_U32 26368   // + 128*68
#define ATTN_SMEM_BYTES (ATTN_SMEM_U32 * 4)

__global__ void __launch_bounds__(256, 2) attn_tc_kernel(
    const float* __restrict__ Q, const float* __restrict__ K,
    const float* __restrict__ V, float* __restrict__ O)
{
    extern __shared__ uint32_t smem_u[];
    uint32_t* sQ = smem_u;
    uint32_t* sK = smem_u + OFF_K;
    uint32_t* sV = smem_u + OFF_V;
    uint32_t* sP = smem_u + OFF_P;

    int tid  = threadIdx.x;
    int warp = tid >> 5;
    int lane = tid & 31;
    int gp = lane >> 2;
    int tg = lane & 3;
    int mw = warp * 16;

    int qt = blockIdx.x;
    int bh = blockIdx.y;
    int b  = bh >> 4;
    int h  = bh & 15;
    size_t base = ((size_t)b * S_) * D_ + (size_t)h * DK_;

    for (int i = tid; i < 128 * 16; i += 256) {
        int r = i >> 4, c4 = (i & 15) * 4;
        float4 v = *(const float4*)(Q + base + (size_t)(qt * 128 + r) * D_ + c4);
        uint32_t q4[4];
        q4[0] = f2tf32(v.x * 0.125f); q4[1] = f2tf32(v.y * 0.125f);
        q4[2] = f2tf32(v.z * 0.125f); q4[3] = f2tf32(v.w * 0.125f);
        *(uint4*)(sQ + r * SQS + c4) = *(uint4*)q4;
    }

    float oacc[8][4];
    #pragma unroll
    for (int n = 0; n < 8; n++)
        #pragma unroll
        for (int c = 0; c < 4; c++) oacc[n][c] = 0.f;
    float m_lo = -INFINITY, m_hi = -INFINITY;
    float l_lo = 0.f, l_hi = 0.f;

    for (int kt = 0; kt < S_ / 64; kt++) {
        for (int i = tid; i < 64 * 16; i += 256) {
            int r = i >> 4, c4 = (i & 15) * 4;
            size_t goff = base + (size_t)(kt * 64 + r) * D_ + c4;
            float4 kv = *(const float4*)(K + goff);
            float4 vv = *(const float4*)(V + goff);
            uint32_t k4[4], v4[4];
            k4[0] = f2tf32(kv.x); k4[1] = f2tf32(kv.y);
            k4[2] = f2tf32(kv.z); k4[3] = f2tf32(kv.w);
            v4[0] = f2tf32(vv.x); v4[1] = f2tf32(vv.y);
            v4[2] = f2tf32(vv.z); v4[3] = f2tf32(vv.w);
            *(uint4*)(sK + r * SKS + c4) = *(uint4*)k4;
            *(uint4*)(sV + r * SVS + c4) = *(uint4*)v4;
        }
        __syncthreads();

        float sacc[8][4];
        #pragma unroll
        for (int n = 0; n < 8; n++)
            #pragma unroll
            for (int c = 0; c < 4; c++) sacc[n][c] = 0.f;

        #pragma unroll
        for (int k = 0; k < 8; k++) {
            uint32_t aq[4];
            const uint32_t* qr = sQ + (mw + gp) * SQS + k * 8 + tg;
            aq[0] = qr[0];
            aq[1] = qr[8 * SQS];
            aq[2] = qr[4];
            aq[3] = qr[8 * SQS + 4];
            #pragma unroll
            for (int n = 0; n < 8; n++) {
                uint32_t bk[2];
                const uint32_t* kr = sK + (n * 8 + gp) * SKS + k * 8 + tg;
                bk[0] = kr[0];
                bk[1] = kr[4];
                mma_tf32(sacc[n], aq, bk);
            }
        }

        float mx_lo = -INFINITY, mx_hi = -INFINITY;
        #pragma unroll
        for (int n = 0; n < 8; n++) {
            mx_lo = fmaxf(mx_lo, fmaxf(sacc[n][0], sacc[n][1]));
            mx_hi = fmaxf(mx_hi, fmaxf(sacc[n][2], sacc[n][3]));
        }
        mx_lo = fmaxf(mx_lo, __shfl_xor_sync(0xffffffffu, mx_lo, 1));
        mx_lo = fmaxf(mx_lo, __shfl_xor_sync(0xffffffffu, mx_lo, 2));
        mx_hi = fmaxf(mx_hi, __shfl_xor_sync(0xffffffffu, mx_hi, 1));
        mx_hi = fmaxf(mx_hi, __shfl_xor_sync(0xffffffffu, mx_hi, 2));

        float mn_lo = fmaxf(m_lo, mx_lo);
        float mn_hi = fmaxf(m_hi, mx_hi);
        float f_lo = __expf(m_lo - mn_lo);
        float f_hi = __expf(m_hi - mn_hi);
        m_lo = mn_lo; m_hi = mn_hi;

        float s_lo = 0.f, s_hi = 0.f;
        uint32_t* plo_base = sP + (mw + gp) * SPS + tg * 2;
        #pragma unroll
        for (int n = 0; n < 8; n++) {
            float p0 = __expf(sacc[n][0] - mn_lo);
            float p1 = __expf(sacc[n][1] - mn_lo);
            float p2 = __expf(sacc[n][2] - mn_hi);
            float p3 = __expf(sacc[n][3] - mn_hi);
            s_lo += p0 + p1;
            s_hi += p2 + p3;
            uint32_t* plo = plo_base + n * 8;
            plo[0] = f2tf32(p0); plo[1] = f2tf32(p1);
            plo[8 * SPS] = f2tf32(p2); plo[8 * SPS + 1] = f2tf32(p3);
        }
        s_lo += __shfl_xor_sync(0xffffffffu, s_lo, 1);
        s_lo += __shfl_xor_sync(0xffffffffu, s_lo, 2);
        s_hi += __shfl_xor_sync(0xffffffffu, s_hi, 1);
        s_hi += __shfl_xor_sync(0xffffffffu, s_hi, 2);
        l_lo = l_lo * f_lo + s_lo;
        l_hi = l_hi * f_hi + s_hi;

        #pragma unroll
        for (int n = 0; n < 8; n++) {
            oacc[n][0] *= f_lo; oacc[n][1] *= f_lo;
            oacc[n][2] *= f_hi; oacc[n][3] *= f_hi;
        }

        __syncwarp();

        #pragma unroll
        for (int k = 0; k < 8; k++) {
            uint32_t ap[4];
            const uint32_t* pr = sP + (mw + gp) * SPS + k * 8 + tg;
            ap[0] = pr[0];
            ap[1] = pr[8 * SPS];
            ap[2] = pr[4];
            ap[3] = pr[8 * SPS + 4];
            #pragma unroll
            for (int n = 0; n < 8; n++) {
                uint32_t bv[2];
                const uint32_t* vr = sV + (k * 8 + tg) * SVS + n * 8 + gp;
                bv[0] = vr[0];
                bv[1] = vr[4 * SVS];
                mma_tf32(oacc[n], ap, bv);
            }
        }
        __syncthreads();
    }

    float inv_lo = 1.f / l_lo;
    float inv_hi = 1.f / l_hi;
    int row_lo = qt * 128 + mw + gp;
    #pragma unroll
    for (int n = 0; n < 8; n++) {
        size_t off_lo = base + (size_t)row_lo * D_ + n * 8 + tg * 2;
        float2 o1; o1.x = rtf(oacc[n][0] * inv_lo); o1.y = rtf(oacc[n][1] * inv_lo);
        *(float2*)(O + off_lo) = o1;
        size_t off_hi = off_lo + (size_t)8 * D_;
        float2 o2; o2.x = rtf(oacc[n][2] * inv_hi); o2.y = rtf(oacc[n][3] * inv_hi);
        *(float2*)(O + off_hi) = o2;
    }
}

// ---------------------------------------------------------------------------
// Launch
// ---------------------------------------------------------------------------
extern "C" void kernel_launch(void* const* d_in, const int* in_sizes, int n_in,
                              void* d_out, int out_size)
{
    const float* x   = (const float*)d_in[0];
    const float* wq  = (const float*)d_in[1];
    const float* wk  = (const float*)d_in[2];
    const float* wv  = (const float*)d_in[3];
    const float* wo  = (const float*)d_in[4];
    const float* w1  = (const float*)d_in[5];
    const float* b1  = (const float*)d_in[6];
    const float* w2  = (const float*)d_in[7];
    const float* b2  = (const float*)d_in[8];
    const float* g1  = (const float*)d_in[9];
    const float* be1 = (const float*)d_in[10];
    const float* g2  = (const float*)d_in[11];
    const float* be2 = (const float*)d_in[12];
    float* out = (float*)d_out;

    float *h, *q, *k, *v, *at, *x1, *h2, *ff;
    float *rwq, *rwk, *rwv, *rwo, *rw1, *rw2;
    cudaGetSymbolAddress((void**)&h,  g_h);
    cudaGetSymbolAddress((void**)&q,  g_q);
    cudaGetSymbolAddress((void**)&k,  g_k);
    cudaGetSymbolAddress((void**)&v,  g_v);
    cudaGetSymbolAddress((void**)&at, g_at);
    cudaGetSymbolAddress((void**)&x1, g_x1);
    cudaGetSymbolAddress((void**)&h2, g_h2);
    cudaGetSymbolAddress((void**)&ff, g_ff);
    cudaGetSymbolAddress((void**)&rwq, g_wq);
    cudaGetSymbolAddress((void**)&rwk, g_wk);
    cudaGetSymbolAddress((void**)&rwv, g_wv);
    cudaGetSymbolAddress((void**)&rwo, g_wo);
    cudaGetSymbolAddress((void**)&rw1, g_w1);
    cudaGetSymbolAddress((void**)&rw2, g_w2);

    // >48KB dynamic smem opt-ins (host-side attributes, idempotent)
    cudaFuncSetAttribute(attn_tc_kernel,
                         cudaFuncAttributeMaxDynamicSharedMemorySize,
                         ATTN_SMEM_BYTES);
    cudaFuncSetAttribute(tf32gemm256_kernel<0,3>,
                         cudaFuncAttributeMaxDynamicSharedMemorySize, GSM_BYTES);
    cudaFuncSetAttribute(tf32gemm256_kernel<4,1>,
                         cudaFuncAttributeMaxDynamicSharedMemorySize, GSM_BYTES);
    cudaFuncSetAttribute(tf32gemm256_kernel<11,1>,
                         cudaFuncAttributeMaxDynamicSharedMemorySize, GSM_BYTES);
    cudaFuncSetAttribute(tf32gemm256_kernel<5,1>,
                         cudaFuncAttributeMaxDynamicSharedMemorySize, GSM_BYTES);

    dim3 blk(256);

    // 0) pre-round weights to tf32 (1-2 float4/thread; ~streaming-BW bound)
    round_w_kernel<<<1024, blk>>>(wq, rwq, D_*D_/4);
    round_w_kernel<<<1024, blk>>>(wk, rwk, D_*D_/4);
    round_w_kernel<<<1024, blk>>>(wv, rwv, D_*D_/4);
    round_w_kernel<<<1024, blk>>>(wo, rwo, D_*D_/4);
    round_w_kernel<<<2048, blk>>>(w1, rw1, D_*DFF_/4);
    round_w_kernel<<<2048, blk>>>(w2, rw2, DFF_*D_/4);

    // 1) h = LN1(x)  (tf32-rounded output)
    ln_kernel<<<NTOK, blk>>>(x, g1, be1, h);

    // 2-4) q,k,v projections: fused QKV
    tf32gemm256_kernel<0,3><<<dim3(24, NTOK/256), blk, GSM_BYTES>>>(
        NTOK, D_, D_, h, rwq, rwk, rwv, nullptr, nullptr, q, k, v);

    // 5) attention (flash, tf32 tensor cores; output tf32-rounded)
    attn_tc_kernel<<<dim3(S_ / 128, B_ * H_), blk, ATTN_SMEM_BYTES>>>(q, k, v, at);

    // 6) x1 = x + attn @ wo
    tf32gemm256_kernel<4,1><<<dim3(D_/128, NTOK/256), blk, GSM_BYTES>>>(
        NTOK, D_, D_, at, rwo, nullptr, nullptr, nullptr, x, x1, nullptr, nullptr);

    // 7) h2 = LN2(x1)  (tf32-rounded output)
    ln_kernel<<<NTOK, blk>>>(x1, g2, be2, h2);

    // 8) ff = relu(h2 @ w1 + b1), rounded to tf32 (EPI 1|2|8 = 11)
    tf32gemm256_kernel<11,1><<<dim3(DFF_/128, NTOK/256), blk, GSM_BYTES>>>(
        NTOK, DFF_, D_, h2, rw1, nullptr, nullptr, b1, nullptr, ff, nullptr, nullptr);

    // 9) out = x1 + ff @ w2 + b2
    tf32gemm256_kernel<5,1><<<dim3(D_/128, NTOK/256), blk, GSM_BYTES>>>(
        NTOK, D_, DFF_, ff, rw2, nullptr, nullptr, b2, x1, out, nullptr, nullptr);
}